// round 1
// baseline (speedup 1.0000x reference)
#include <cuda_runtime.h>
#include <math.h>

#define NTOK 8192
#define DM 1024
#define DF 4096
#define NE 8
#define BM 128
#define MAXROWS (NTOK*2 + NE*BM)   /* 17408 */
#define MT (MAXROWS/BM)            /* 136 */

// ---------------- scratch (device globals: allocation-free) ----------------
__device__ __align__(16) float g_h[(size_t)MAXROWS * DF];   // post-ReLU activations
__device__ __align__(16) float g_y[(size_t)MAXROWS * DM];   // scaled expert outputs
__device__ int   g_atok[MAXROWS];      // slot -> token (-1 = padding)
__device__ float g_aw[MAXROWS];        // slot -> gate weight
__device__ int   g_tokslot[NTOK * 2];  // token -> its 2 slots
__device__ int   g_t2e[NTOK * 2];
__device__ float g_t2w[NTOK * 2];
__device__ int   g_cnt[NE];
__device__ int   g_fill[NE];
__device__ int   g_off[NE + 1];

// ---------------- init ----------------
__global__ void k_init() {
    int i = blockIdx.x * blockDim.x + threadIdx.x;
    if (i < MAXROWS) g_atok[i] = -1;
    if (i < NE) { g_cnt[i] = 0; g_fill[i] = 0; }
}

// ---------------- gating: logits -> softmax -> top2 ----------------
__global__ __launch_bounds__(256) void k_gate(const float* __restrict__ x,
                                              const float* __restrict__ gw,
                                              const float* __restrict__ gb) {
    __shared__ float sgw[DM * NE];
    int tid = threadIdx.x;
    for (int i = tid; i < DM * NE; i += 256) sgw[i] = gw[i];
    __syncthreads();

    int warp = tid >> 5, lane = tid & 31;
    int t = blockIdx.x * 8 + warp;
    const float* xr = x + (size_t)t * DM;

    float acc[NE];
#pragma unroll
    for (int e = 0; e < NE; e++) acc[e] = 0.f;
    for (int d = lane; d < DM; d += 32) {
        float xv = xr[d];
#pragma unroll
        for (int e = 0; e < NE; e++) acc[e] = fmaf(xv, sgw[d * NE + e], acc[e]);
    }
#pragma unroll
    for (int off = 16; off; off >>= 1)
#pragma unroll
        for (int e = 0; e < NE; e++) acc[e] += __shfl_xor_sync(0xFFFFFFFFu, acc[e], off);

    if (lane == 0) {
        float lg[NE], m = -1e30f;
#pragma unroll
        for (int e = 0; e < NE; e++) { lg[e] = acc[e] + gb[e]; m = fmaxf(m, lg[e]); }
        float ex[NE], s = 0.f;
#pragma unroll
        for (int e = 0; e < NE; e++) { ex[e] = expf(lg[e] - m); s += ex[e]; }
        int e0 = 0;
#pragma unroll
        for (int e = 1; e < NE; e++) if (ex[e] > ex[e0]) e0 = e;
        int e1 = (e0 == 0) ? 1 : 0;
#pragma unroll
        for (int e = 0; e < NE; e++) if (e != e0 && ex[e] > ex[e1]) e1 = e;
        float inv = 1.f / s;
        g_t2e[2 * t] = e0;     g_t2w[2 * t] = ex[e0] * inv;
        g_t2e[2 * t + 1] = e1; g_t2w[2 * t + 1] = ex[e1] * inv;
        atomicAdd(&g_cnt[e0], 1);
        atomicAdd(&g_cnt[e1], 1);
    }
}

// ---------------- per-expert tile-aligned offsets ----------------
__global__ void k_off() {
    g_off[0] = 0;
    for (int e = 0; e < NE; e++)
        g_off[e + 1] = g_off[e] + (((g_cnt[e] + BM - 1) / BM) * BM);
}

// ---------------- scatter tokens into expert segments ----------------
__global__ void k_scatter() {
    int t = blockIdx.x * blockDim.x + threadIdx.x;
    if (t >= NTOK) return;
#pragma unroll
    for (int r = 0; r < 2; r++) {
        int e = g_t2e[2 * t + r];
        int p = atomicAdd(&g_fill[e], 1);
        int s = g_off[e] + p;
        g_atok[s] = t;
        g_aw[s] = g_t2w[2 * t + r];
        g_tokslot[2 * t + r] = s;
    }
}

// ---------------- GEMM1: h = relu(x[tok] @ w1[e] + b1[e]) ----------------
__global__ __launch_bounds__(256) void k_ffn1(const float* __restrict__ x,
                                              const float* __restrict__ w1,
                                              const float* __restrict__ b1) {
    __shared__ float As[8][132];
    __shared__ float Bs[8][128];
    __shared__ int stok[BM];

    int row0 = blockIdx.y * BM;
    if (row0 >= g_off[NE]) return;
    int e = 0;
#pragma unroll
    for (int i = 0; i < NE - 1; i++) if (g_off[i + 1] <= row0) e = i + 1;

    int tid = threadIdx.x;
    if (tid < BM) stok[tid] = g_atok[row0 + tid];
    __syncthreads();

    const float* w1e = w1 + (size_t)e * DM * DF;
    int col0 = blockIdx.x * 128;
    int tx = tid & 15, ty = tid >> 4;
    int am = tid >> 1, akq = (tid & 1) * 4;
    int bk = tid >> 5, bn = (tid & 31) * 4;
    int tok = stok[am];
    const float* aptr = (tok >= 0) ? (x + (size_t)tok * DM + akq) : 0;

    float acc[8][8] = {};

    for (int kb = 0; kb < DM; kb += 8) {
        float4 av = make_float4(0.f, 0.f, 0.f, 0.f);
        if (aptr) av = *(const float4*)(aptr + kb);
        float4 bv = *(const float4*)(w1e + (size_t)(kb + bk) * DF + col0 + bn);
        __syncthreads();
        As[akq + 0][am] = av.x; As[akq + 1][am] = av.y;
        As[akq + 2][am] = av.z; As[akq + 3][am] = av.w;
        *(float4*)&Bs[bk][bn] = bv;
        __syncthreads();
#pragma unroll
        for (int k = 0; k < 8; k++) {
            float4 a0 = *(const float4*)&As[k][ty * 8];
            float4 a1 = *(const float4*)&As[k][ty * 8 + 4];
            float4 b0 = *(const float4*)&Bs[k][tx * 8];
            float4 b1v = *(const float4*)&Bs[k][tx * 8 + 4];
            float a[8] = {a0.x, a0.y, a0.z, a0.w, a1.x, a1.y, a1.z, a1.w};
            float b[8] = {b0.x, b0.y, b0.z, b0.w, b1v.x, b1v.y, b1v.z, b1v.w};
#pragma unroll
            for (int i = 0; i < 8; i++)
#pragma unroll
                for (int j = 0; j < 8; j++)
                    acc[i][j] = fmaf(a[i], b[j], acc[i][j]);
        }
    }

    float4 bias0 = *(const float4*)(b1 + (size_t)e * DF + col0 + tx * 8);
    float4 bias1 = *(const float4*)(b1 + (size_t)e * DF + col0 + tx * 8 + 4);
#pragma unroll
    for (int i = 0; i < 8; i++) {
        int row = row0 + ty * 8 + i;
        float4* dst = (float4*)(g_h + (size_t)row * DF + col0 + tx * 8);
        float4 v0, v1;
        v0.x = fmaxf(acc[i][0] + bias0.x, 0.f);
        v0.y = fmaxf(acc[i][1] + bias0.y, 0.f);
        v0.z = fmaxf(acc[i][2] + bias0.z, 0.f);
        v0.w = fmaxf(acc[i][3] + bias0.w, 0.f);
        v1.x = fmaxf(acc[i][4] + bias1.x, 0.f);
        v1.y = fmaxf(acc[i][5] + bias1.y, 0.f);
        v1.z = fmaxf(acc[i][6] + bias1.z, 0.f);
        v1.w = fmaxf(acc[i][7] + bias1.w, 0.f);
        dst[0] = v0; dst[1] = v1;
    }
}

// ---------------- GEMM2: y = (h @ w2[e] + b2[e]) * gate_w ----------------
__global__ __launch_bounds__(256) void k_ffn2(const float* __restrict__ w2,
                                              const float* __restrict__ b2) {
    __shared__ float As[8][132];
    __shared__ float Bs[8][128];

    int row0 = blockIdx.y * BM;
    if (row0 >= g_off[NE]) return;
    int e = 0;
#pragma unroll
    for (int i = 0; i < NE - 1; i++) if (g_off[i + 1] <= row0) e = i + 1;

    int tid = threadIdx.x;
    const float* w2e = w2 + (size_t)e * DF * DM;
    int col0 = blockIdx.x * 128;
    int tx = tid & 15, ty = tid >> 4;
    int am = tid >> 1, akq = (tid & 1) * 4;
    int bk = tid >> 5, bn = (tid & 31) * 4;
    const float* aptr = g_h + (size_t)(row0 + am) * DF + akq;

    float acc[8][8] = {};

    for (int kb = 0; kb < DF; kb += 8) {
        float4 av = *(const float4*)(aptr + kb);
        float4 bv = *(const float4*)(w2e + (size_t)(kb + bk) * DM + col0 + bn);
        __syncthreads();
        As[akq + 0][am] = av.x; As[akq + 1][am] = av.y;
        As[akq + 2][am] = av.z; As[akq + 3][am] = av.w;
        *(float4*)&Bs[bk][bn] = bv;
        __syncthreads();
#pragma unroll
        for (int k = 0; k < 8; k++) {
            float4 a0 = *(const float4*)&As[k][ty * 8];
            float4 a1 = *(const float4*)&As[k][ty * 8 + 4];
            float4 b0 = *(const float4*)&Bs[k][tx * 8];
            float4 b1v = *(const float4*)&Bs[k][tx * 8 + 4];
            float a[8] = {a0.x, a0.y, a0.z, a0.w, a1.x, a1.y, a1.z, a1.w};
            float b[8] = {b0.x, b0.y, b0.z, b0.w, b1v.x, b1v.y, b1v.z, b1v.w};
#pragma unroll
            for (int i = 0; i < 8; i++)
#pragma unroll
                for (int j = 0; j < 8; j++)
                    acc[i][j] = fmaf(a[i], b[j], acc[i][j]);
        }
    }

    float4 bias0 = *(const float4*)(b2 + (size_t)e * DM + col0 + tx * 8);
    float4 bias1 = *(const float4*)(b2 + (size_t)e * DM + col0 + tx * 8 + 4);
#pragma unroll
    for (int i = 0; i < 8; i++) {
        int row = row0 + ty * 8 + i;
        float sc = g_aw[row];
        float4* dst = (float4*)(g_y + (size_t)row * DM + col0 + tx * 8);
        float4 v0, v1;
        v0.x = (acc[i][0] + bias0.x) * sc;
        v0.y = (acc[i][1] + bias0.y) * sc;
        v0.z = (acc[i][2] + bias0.z) * sc;
        v0.w = (acc[i][3] + bias0.w) * sc;
        v1.x = (acc[i][4] + bias1.x) * sc;
        v1.y = (acc[i][5] + bias1.y) * sc;
        v1.z = (acc[i][6] + bias1.z) * sc;
        v1.w = (acc[i][7] + bias1.w) * sc;
        dst[0] = v0; dst[1] = v1;
    }
}

// ---------------- combine the two expert outputs per token ----------------
__global__ __launch_bounds__(256) void k_combine(float* __restrict__ out) {
    int t = blockIdx.x;
    int d = threadIdx.x;           // float4 index within row (1024/4 = 256)
    int s0 = g_tokslot[2 * t], s1 = g_tokslot[2 * t + 1];
    const float4* y0 = (const float4*)(g_y + (size_t)s0 * DM);
    const float4* y1 = (const float4*)(g_y + (size_t)s1 * DM);
    float4 a = y0[d], b = y1[d];
    ((float4*)out)[(size_t)t * (DM / 4) + d] =
        make_float4(a.x + b.x, a.y + b.y, a.z + b.z, a.w + b.w);
}

// ---------------- launch ----------------
extern "C" void kernel_launch(void* const* d_in, const int* in_sizes, int n_in,
                              void* d_out, int out_size) {
    const float* x  = (const float*)d_in[0];
    const float* gw = (const float*)d_in[1];
    const float* gb = (const float*)d_in[2];
    const float* w1 = (const float*)d_in[3];
    const float* b1 = (const float*)d_in[4];
    const float* w2 = (const float*)d_in[5];
    const float* b2 = (const float*)d_in[6];
    float* out = (float*)d_out;

    k_init<<<(MAXROWS + 255) / 256, 256>>>();
    k_gate<<<NTOK / 8, 256>>>(x, gw, gb);
    k_off<<<1, 1>>>();
    k_scatter<<<(NTOK + 255) / 256, 256>>>();
    k_ffn1<<<dim3(DF / 128, MT), 256>>>(x, w1, b1);
    k_ffn2<<<dim3(DM / 128, MT), 256>>>(w2, b2);
    k_combine<<<NTOK, 256>>>(out);
}

// round 4
// speedup vs baseline: 2.5427x; 2.5427x over previous
#include <cuda_runtime.h>
#include <cuda_bf16.h>
#include <math.h>
#include <stdint.h>

#define NTOK 8192
#define DM 1024
#define DF 4096
#define NE 8
#define BM 128
#define BN 128
#define BK 64
#define MAXROWS (NTOK*2 + NE*BM)   /* 17408 */
#define MT (MAXROWS/BM)            /* 136 */

// smem stage layout: 4 tiles of 128 rows x 128 bytes (16KB each)
#define AH_OFF 0
#define AL_OFF 16384
#define BH_OFF 32768
#define BL_OFF 49152
#define ST_SIZE 65536
#define SMEM_BYTES (1024 + 2*ST_SIZE)   /* 132096, padded for alignment */

// ---------------- scratch (device globals: allocation-free) ----------------
__device__ __align__(16) __nv_bfloat16 g_xh[(size_t)MAXROWS * DM];
__device__ __align__(16) __nv_bfloat16 g_xl[(size_t)MAXROWS * DM];
__device__ __align__(16) __nv_bfloat16 g_hh[(size_t)MAXROWS * DF];
__device__ __align__(16) __nv_bfloat16 g_hl[(size_t)MAXROWS * DF];
__device__ __align__(16) __nv_bfloat16 g_w1h[(size_t)NE * DF * DM];
__device__ __align__(16) __nv_bfloat16 g_w1l[(size_t)NE * DF * DM];
__device__ __align__(16) __nv_bfloat16 g_w2h[(size_t)NE * DM * DF];
__device__ __align__(16) __nv_bfloat16 g_w2l[(size_t)NE * DM * DF];
__device__ __align__(16) float g_y[(size_t)MAXROWS * DM];
__device__ int   g_atok[MAXROWS];
__device__ float g_aw[MAXROWS];
__device__ int   g_tokslot[NTOK * 2];
__device__ int   g_t2e[NTOK * 2];
__device__ float g_t2w[NTOK * 2];
__device__ int   g_cnt[NE];
__device__ int   g_fill[NE];
__device__ int   g_off[NE + 1];

// ---------------- helpers ----------------
__device__ __forceinline__ uint32_t smem_u32(const void* p) {
    uint32_t a;
    asm("{ .reg .u64 t; cvta.to.shared.u64 t, %1; cvt.u32.u64 %0, t; }" : "=r"(a) : "l"(p));
    return a;
}
#define SWZ(x) ((uint32_t)(x) ^ ((((uint32_t)(x)) >> 3) & 0x70))

__device__ __forceinline__ void cp16(uint32_t dst, const void* src) {
    asm volatile("cp.async.cg.shared.global [%0], [%1], 16;" :: "r"(dst), "l"(src));
}
#define CP_COMMIT() asm volatile("cp.async.commit_group;" ::: "memory")
#define CP_WAIT1()  asm volatile("cp.async.wait_group 1;" ::: "memory")
#define CP_WAIT0()  asm volatile("cp.async.wait_group 0;" ::: "memory")

__device__ __forceinline__ void ldm4(uint32_t* r, uint32_t addr) {
    asm volatile("ldmatrix.sync.aligned.m8n8.x4.shared.b16 {%0,%1,%2,%3}, [%4];"
        : "=r"(r[0]), "=r"(r[1]), "=r"(r[2]), "=r"(r[3]) : "r"(addr));
}
__device__ __forceinline__ void mma16816(float* c, const uint32_t* a, uint32_t b0, uint32_t b1) {
    asm volatile("mma.sync.aligned.m16n8k16.row.col.f32.bf16.bf16.f32 "
        "{%0,%1,%2,%3}, {%4,%5,%6,%7}, {%8,%9}, {%0,%1,%2,%3};"
        : "+f"(c[0]), "+f"(c[1]), "+f"(c[2]), "+f"(c[3])
        : "r"(a[0]), "r"(a[1]), "r"(a[2]), "r"(a[3]), "r"(b0), "r"(b1));
}

// ---------------- init ----------------
__global__ void k_init() {
    int i = blockIdx.x * blockDim.x + threadIdx.x;
    if (i < MAXROWS) g_atok[i] = -1;
    if (i < NE) { g_cnt[i] = 0; g_fill[i] = 0; }
}

// ---------------- gating ----------------
__global__ __launch_bounds__(256) void k_gate(const float* __restrict__ x,
                                              const float* __restrict__ gw,
                                              const float* __restrict__ gb) {
    __shared__ float sgw[DM * NE];
    int tid = threadIdx.x;
    for (int i = tid; i < DM * NE; i += 256) sgw[i] = gw[i];
    __syncthreads();
    int warp = tid >> 5, lane = tid & 31;
    int t = blockIdx.x * 8 + warp;
    const float* xr = x + (size_t)t * DM;
    float acc[NE];
#pragma unroll
    for (int e = 0; e < NE; e++) acc[e] = 0.f;
    for (int d = lane; d < DM; d += 32) {
        float xv = xr[d];
#pragma unroll
        for (int e = 0; e < NE; e++) acc[e] = fmaf(xv, sgw[d * NE + e], acc[e]);
    }
#pragma unroll
    for (int off = 16; off; off >>= 1)
#pragma unroll
        for (int e = 0; e < NE; e++) acc[e] += __shfl_xor_sync(0xFFFFFFFFu, acc[e], off);
    if (lane == 0) {
        float lg[NE], m = -1e30f;
#pragma unroll
        for (int e = 0; e < NE; e++) { lg[e] = acc[e] + gb[e]; m = fmaxf(m, lg[e]); }
        float ex[NE], s = 0.f;
#pragma unroll
        for (int e = 0; e < NE; e++) { ex[e] = expf(lg[e] - m); s += ex[e]; }
        int e0 = 0;
#pragma unroll
        for (int e = 1; e < NE; e++) if (ex[e] > ex[e0]) e0 = e;
        int e1 = (e0 == 0) ? 1 : 0;
#pragma unroll
        for (int e = 0; e < NE; e++) if (e != e0 && ex[e] > ex[e1]) e1 = e;
        float inv = 1.f / s;
        g_t2e[2 * t] = e0;     g_t2w[2 * t] = ex[e0] * inv;
        g_t2e[2 * t + 1] = e1; g_t2w[2 * t + 1] = ex[e1] * inv;
        atomicAdd(&g_cnt[e0], 1);
        atomicAdd(&g_cnt[e1], 1);
    }
}

__global__ void k_off() {
    g_off[0] = 0;
    for (int e = 0; e < NE; e++)
        g_off[e + 1] = g_off[e] + (((g_cnt[e] + BM - 1) / BM) * BM);
}

__global__ void k_scatter() {
    int t = blockIdx.x * blockDim.x + threadIdx.x;
    if (t >= NTOK) return;
#pragma unroll
    for (int r = 0; r < 2; r++) {
        int e = g_t2e[2 * t + r];
        int p = atomicAdd(&g_fill[e], 1);
        int s = g_off[e] + p;
        g_atok[s] = t;
        g_aw[s] = g_t2w[2 * t + r];
        g_tokslot[2 * t + r] = s;
    }
}

// ---------------- gather + hi/lo split activations ----------------
__global__ __launch_bounds__(256) void k_actsplit(const float* __restrict__ x) {
    int slot = blockIdx.x;
    int tok = g_atok[slot];
    int t4 = threadIdx.x;
    float4 v = make_float4(0.f, 0.f, 0.f, 0.f);
    if (tok >= 0) v = ((const float4*)(x + (size_t)tok * DM))[t4];
    float vv[4] = {v.x, v.y, v.z, v.w};
    __nv_bfloat16 h[4], l[4];
#pragma unroll
    for (int i = 0; i < 4; i++) {
        h[i] = __float2bfloat16(vv[i]);
        l[i] = __float2bfloat16(vv[i] - __bfloat162float(h[i]));
    }
    size_t base = (size_t)slot * DM + t4 * 4;
    __nv_bfloat162 hp0; hp0.x = h[0]; hp0.y = h[1];
    __nv_bfloat162 hp1; hp1.x = h[2]; hp1.y = h[3];
    __nv_bfloat162 lp0; lp0.x = l[0]; lp0.y = l[1];
    __nv_bfloat162 lp1; lp1.x = l[2]; lp1.y = l[3];
    *(__nv_bfloat162*)(g_xh + base)     = hp0;
    *(__nv_bfloat162*)(g_xh + base + 2) = hp1;
    *(__nv_bfloat162*)(g_xl + base)     = lp0;
    *(__nv_bfloat162*)(g_xl + base + 2) = lp1;
}

// ---------------- transpose + hi/lo split weights ----------------
// Device helper: src [e][K][N] (N contiguous) -> dst globals [e][N][K] (K contiguous).
// NOTE: output arrays are referenced as device globals INSIDE device code —
// never passed from host (host-side &g_* is the shadow symbol, round-3 bug).
template <int K, int N, bool IS_W1>
__global__ __launch_bounds__(256) void k_wsplit_t(const float* __restrict__ w) {
    __shared__ float tile[32][33];
    int e = blockIdx.z;
    int n0 = blockIdx.x * 32, k0 = blockIdx.y * 32;
    int tx = threadIdx.x, ty = threadIdx.y;
    const float* we = w + (size_t)e * K * N;
    for (int i = ty; i < 32; i += 8)
        tile[i][tx] = we[(size_t)(k0 + i) * N + n0 + tx];
    __syncthreads();
    __nv_bfloat16* ohe = (IS_W1 ? g_w1h : g_w2h) + (size_t)e * N * K;
    __nv_bfloat16* ole = (IS_W1 ? g_w1l : g_w2l) + (size_t)e * N * K;
    for (int i = ty; i < 32; i += 8) {
        float v = tile[tx][i];
        __nv_bfloat16 h = __float2bfloat16(v);
        __nv_bfloat16 l = __float2bfloat16(v - __bfloat162float(h));
        size_t o = (size_t)(n0 + i) * K + k0 + tx;
        ohe[o] = h;
        ole[o] = l;
    }
}

// ================= shared HMMA mainloop =================
// A tile [BM][BK] row-major, B tile [BN][BK] (n-major, k-contig == col-major B)
struct Acc { float v[4][4][4]; };   // [mi][ni][frag]

__device__ __forceinline__ void hmma_mainloop(
    uint32_t sb, Acc& A,
    const __nv_bfloat16* Ah, const __nv_bfloat16* Al, int astride,
    const __nv_bfloat16* Bh, const __nv_bfloat16* Bl, int bstride,
    int NC, int tid)
{
    int wid = tid >> 5, L = tid & 31;
    int wm = wid & 1, wn = wid >> 1;   // 2 x 4 warp grid, warp tile 64x32

    int fr = tid & 127;                // fill row
    int hb = (tid >> 7) * 64;          // fill byte half within 128B row

    auto fill = [&](int s, int c) {
        uint32_t st = sb + s * ST_SIZE;
        const char* pah = (const char*)(Ah + (size_t)fr * astride + c * BK) + hb;
        const char* pal = (const char*)(Al + (size_t)fr * astride + c * BK) + hb;
        const char* pbh = (const char*)(Bh + (size_t)fr * bstride + c * BK) + hb;
        const char* pbl = (const char*)(Bl + (size_t)fr * bstride + c * BK) + hb;
        uint32_t rb = fr * 128 + hb;
#pragma unroll
        for (int j = 0; j < 4; j++) {
            uint32_t o = SWZ(rb + j * 16);
            cp16(st + AH_OFF + o, pah + j * 16);
            cp16(st + AL_OFF + o, pal + j * 16);
            cp16(st + BH_OFF + o, pbh + j * 16);
            cp16(st + BL_OFF + o, pbl + j * 16);
        }
    };

    fill(0, 0); CP_COMMIT();
    fill(1, 1); CP_COMMIT();

    int lrow = L & 15;            // row within 16-row group
    int lkb = (L >> 4) * 16;      // 16B column half

    for (int c = 0; c < NC; c++) {
        int s = c & 1;
        if (c + 1 < NC) CP_WAIT1(); else CP_WAIT0();
        __syncthreads();
        uint32_t st = sb + s * ST_SIZE;

#pragma unroll
        for (int ks = 0; ks < 4; ks++) {
            uint32_t kb = ks * 32 + lkb;
            uint32_t ah[4][4], al[4][4], bh[2][4], bl[2][4];
#pragma unroll
            for (int mi = 0; mi < 4; mi++) {
                uint32_t ro = (wm * 64 + mi * 16 + lrow) * 128 + kb;
                ldm4(ah[mi], st + AH_OFF + SWZ(ro));
                ldm4(al[mi], st + AL_OFF + SWZ(ro));
            }
#pragma unroll
            for (int nj = 0; nj < 2; nj++) {
                uint32_t ro = (wn * 32 + nj * 16 + lrow) * 128 + kb;
                ldm4(bh[nj], st + BH_OFF + SWZ(ro));
                ldm4(bl[nj], st + BL_OFF + SWZ(ro));
            }
#pragma unroll
            for (int mi = 0; mi < 4; mi++)
#pragma unroll
                for (int ni = 0; ni < 4; ni++) {
                    int nj = ni >> 1, hf = ni & 1;
                    float* acc = A.v[mi][ni];
                    mma16816(acc, ah[mi], bh[nj][hf], bh[nj][hf + 2]);
                    mma16816(acc, ah[mi], bl[nj][hf], bl[nj][hf + 2]);
                    mma16816(acc, al[mi], bh[nj][hf], bh[nj][hf + 2]);
                }
        }
        __syncthreads();
        if (c + 2 < NC) { fill(s, c + 2); CP_COMMIT(); }
    }
}

// ---------------- GEMM1: h = relu(x @ w1 + b1), split to bf16 hi/lo ----------------
__global__ __launch_bounds__(256, 1) void k_mma1(const float* __restrict__ b1) {
    extern __shared__ char smem[];
    int row0 = blockIdx.y * BM;
    if (row0 >= g_off[NE]) return;
    int e = 0;
#pragma unroll
    for (int i = 0; i < NE - 1; i++) if (g_off[i + 1] <= row0) e = i + 1;
    int col0 = blockIdx.x * BN;
    uint32_t sb = (smem_u32(smem) + 1023) & ~1023u;
    int tid = threadIdx.x;

    Acc A;
#pragma unroll
    for (int i = 0; i < 4; i++)
#pragma unroll
        for (int j = 0; j < 4; j++)
#pragma unroll
            for (int k = 0; k < 4; k++) A.v[i][j][k] = 0.f;

    hmma_mainloop(sb, A,
                  g_xh + (size_t)row0 * DM, g_xl + (size_t)row0 * DM, DM,
                  g_w1h + (size_t)e * DF * DM + (size_t)col0 * DM,
                  g_w1l + (size_t)e * DF * DM + (size_t)col0 * DM, DM,
                  DM / BK, tid);

    int wid = tid >> 5, L = tid & 31;
    int wm = wid & 1, wn = wid >> 1;
    const float* b1e = b1 + (size_t)e * DF;
#pragma unroll
    for (int mi = 0; mi < 4; mi++) {
        int r0 = row0 + wm * 64 + mi * 16 + (L >> 2);
#pragma unroll
        for (int ni = 0; ni < 4; ni++) {
            int col = col0 + wn * 32 + ni * 8 + (L & 3) * 2;
            float bb0 = b1e[col], bb1 = b1e[col + 1];
            float* a = A.v[mi][ni];
#pragma unroll
            for (int hrow = 0; hrow < 2; hrow++) {
                int row = r0 + hrow * 8;
                float v0 = fmaxf(a[hrow * 2 + 0] + bb0, 0.f);
                float v1 = fmaxf(a[hrow * 2 + 1] + bb1, 0.f);
                __nv_bfloat16 h0 = __float2bfloat16(v0);
                __nv_bfloat16 h1 = __float2bfloat16(v1);
                __nv_bfloat162 hp; hp.x = h0; hp.y = h1;
                __nv_bfloat162 lp;
                lp.x = __float2bfloat16(v0 - __bfloat162float(h0));
                lp.y = __float2bfloat16(v1 - __bfloat162float(h1));
                size_t o = (size_t)row * DF + col;
                *(__nv_bfloat162*)(g_hh + o) = hp;
                *(__nv_bfloat162*)(g_hl + o) = lp;
            }
        }
    }
}

// ---------------- GEMM2: y = (h @ w2 + b2) * gate ----------------
__global__ __launch_bounds__(256, 1) void k_mma2(const float* __restrict__ b2) {
    extern __shared__ char smem[];
    int row0 = blockIdx.y * BM;
    if (row0 >= g_off[NE]) return;
    int e = 0;
#pragma unroll
    for (int i = 0; i < NE - 1; i++) if (g_off[i + 1] <= row0) e = i + 1;
    int col0 = blockIdx.x * BN;
    uint32_t sb = (smem_u32(smem) + 1023) & ~1023u;
    int tid = threadIdx.x;

    Acc A;
#pragma unroll
    for (int i = 0; i < 4; i++)
#pragma unroll
        for (int j = 0; j < 4; j++)
#pragma unroll
            for (int k = 0; k < 4; k++) A.v[i][j][k] = 0.f;

    hmma_mainloop(sb, A,
                  g_hh + (size_t)row0 * DF, g_hl + (size_t)row0 * DF, DF,
                  g_w2h + (size_t)e * DM * DF + (size_t)col0 * DF,
                  g_w2l + (size_t)e * DM * DF + (size_t)col0 * DF, DF,
                  DF / BK, tid);

    int wid = tid >> 5, L = tid & 31;
    int wm = wid & 1, wn = wid >> 1;
    const float* b2e = b2 + (size_t)e * DM;
#pragma unroll
    for (int mi = 0; mi < 4; mi++) {
        int r0 = row0 + wm * 64 + mi * 16 + (L >> 2);
#pragma unroll
        for (int ni = 0; ni < 4; ni++) {
            int col = col0 + wn * 32 + ni * 8 + (L & 3) * 2;
            float bb0 = b2e[col], bb1 = b2e[col + 1];
            float* a = A.v[mi][ni];
#pragma unroll
            for (int hrow = 0; hrow < 2; hrow++) {
                int row = r0 + hrow * 8;
                float sc = g_aw[row];
                float2 v;
                v.x = (a[hrow * 2 + 0] + bb0) * sc;
                v.y = (a[hrow * 2 + 1] + bb1) * sc;
                *(float2*)(g_y + (size_t)row * DM + col) = v;
            }
        }
    }
}

// ---------------- combine ----------------
__global__ __launch_bounds__(256) void k_combine(float* __restrict__ out) {
    int t = blockIdx.x;
    int d = threadIdx.x;
    int s0 = g_tokslot[2 * t], s1 = g_tokslot[2 * t + 1];
    const float4* y0 = (const float4*)(g_y + (size_t)s0 * DM);
    const float4* y1 = (const float4*)(g_y + (size_t)s1 * DM);
    float4 a = y0[d], b = y1[d];
    ((float4*)out)[(size_t)t * (DM / 4) + d] =
        make_float4(a.x + b.x, a.y + b.y, a.z + b.z, a.w + b.w);
}

// ---------------- launch ----------------
extern "C" void kernel_launch(void* const* d_in, const int* in_sizes, int n_in,
                              void* d_out, int out_size) {
    const float* x  = (const float*)d_in[0];
    const float* gw = (const float*)d_in[1];
    const float* gb = (const float*)d_in[2];
    const float* w1 = (const float*)d_in[3];
    const float* b1 = (const float*)d_in[4];
    const float* w2 = (const float*)d_in[5];
    const float* b2 = (const float*)d_in[6];
    float* out = (float*)d_out;

    cudaFuncSetAttribute(k_mma1, cudaFuncAttributeMaxDynamicSharedMemorySize, SMEM_BYTES);
    cudaFuncSetAttribute(k_mma2, cudaFuncAttributeMaxDynamicSharedMemorySize, SMEM_BYTES);

    k_init<<<(MAXROWS + 255) / 256, 256>>>();
    k_gate<<<NTOK / 8, 256>>>(x, gw, gb);
    k_off<<<1, 1>>>();
    k_scatter<<<(NTOK + 255) / 256, 256>>>();
    k_actsplit<<<MAXROWS, 256>>>(x);
    k_wsplit_t<DM, DF, true><<<dim3(DF / 32, DM / 32, NE), dim3(32, 8)>>>(w1);
    k_wsplit_t<DF, DM, false><<<dim3(DM / 32, DF / 32, NE), dim3(32, 8)>>>(w2);
    k_mma1<<<dim3(DF / BN, MT), 256, SMEM_BYTES>>>(b1);
    k_mma2<<<dim3(DM / BN, MT), 256, SMEM_BYTES>>>(b2);
    k_combine<<<NTOK, 256>>>(out);
}